// round 10
// baseline (speedup 1.0000x reference)
#include <cuda_runtime.h>
#include <cstdint>

// ---------------------------------------------------------------------------
// Compile-time LUT construction (replicates the numpy table builders exactly)
// ---------------------------------------------------------------------------
struct LUTs {
    int tbl64[64];   // packed: ptype | rot<<2 | flip<<4, keyed by 6 pairwise <= bits
    int wA[17], wB[17], wC[17];  // lex-rank prefix tables for sorted tuples
};

static constexpr LUTs make_luts() {
    LUTs L = {};
    int tm[256] = {}, rm[256] = {}, fm[256] = {};
    for (int i = 0; i < 256; i++) { tm[i] = 10; rm[i] = 10; fm[i] = 10; }
    const int pats[3][4] = { {0,1,2,3}, {0,1,3,2}, {0,2,3,1} };
    for (int pt = 0; pt < 3; ++pt) {
        int p[4] = { pats[pt][0], pats[pt][1], pats[pt][2], pats[pt][3] };
        for (int fl = 0; fl < 2; ++fl) {
            for (int ro = 0; ro < 4; ++ro) {
                int q[4] = { p[0], p[1], p[2], p[3] };
                for (int k = 0; k < ro; k++) {           // np.rot90 once
                    int t0 = q[0], t1 = q[1], t2 = q[2], t3 = q[3];
                    q[0] = t1; q[1] = t3; q[2] = t0; q[3] = t2;
                }
                int id = ((q[0]*4 + q[1])*4 + q[2])*4 + q[3];
                tm[id] = pt; rm[id] = ro; fm[id] = fl;
            }
            int t0 = p[0], t1 = p[1], t2 = p[2], t3 = p[3]; // p = p[:, ::-1]
            p[0] = t1; p[1] = t0; p[2] = t3; p[3] = t2;
        }
    }
    for (int key = 0; key < 64; ++key) {
        int p01 =  key       & 1;
        int p02 = (key >> 1) & 1;
        int p03 = (key >> 2) & 1;
        int p12 = (key >> 3) & 1;
        int p13 = (key >> 4) & 1;
        int p23 = (key >> 5) & 1;
        int r0 = (1-p01) + (1-p02) + (1-p03);
        int r1 = p01 + (1-p12) + (1-p13);
        int r2 = p02 + p12 + (1-p23);
        int r3 = p03 + p13 + p23;
        int rr[4] = { r0, r1, r2, r3 };
        int seen[4] = {0,0,0,0};
        bool ok = true;
        for (int k = 0; k < 4; k++) {
            if (rr[k] < 0 || rr[k] > 3) { ok = false; break; }
            seen[rr[k]]++;
        }
        if (ok) for (int k = 0; k < 4; k++) if (seen[k] != 1) ok = false;
        int val = 0;
        if (ok) {
            int id = ((r0*4 + r1)*4 + r2)*4 + r3;
            int ty = tm[id], ro = rm[id], fl = fm[id];
            if (ty > 2) ty = 2;
            if (ro > 3) ro = 0;
            if (fl > 1) fl = 0;
            val = ty | (ro << 2) | (fl << 4);
        }
        L.tbl64[key] = val;
    }
    int S1 = 0, S2 = 0, S3 = 0;
    for (int x = 0; x < 17; ++x) {
        L.wA[x] = S3 - S2;
        L.wB[x] = S2 - S1;
        L.wC[x] = S1 - x;
        S1 += 17 - x;
        S2 += (18 - x) * (17 - x) / 2;
        S3 += (19 - x) * (18 - x) * (17 - x) / 6;
    }
    return L;
}

__constant__ LUTs g_luts = make_luts();

// Materialized output, quantized to int8 (values are exact integers in
// [-128,127] after round+clip). 17^4 tiles * 16 B = 1.3 MiB -> L2-resident.
// Layout: g_tab8[v*4 + r] packs row r of tile v as 4 s8 bytes (j=0 in LSB).
#define NVALS 83521
__device__ unsigned g_tab8[NVALS * 4];

// ---------------------------------------------------------------------------
// Shared builder math: packed s8 word for (value v, row r).
// Per-lane row/col source walk, verified rounds 5-9.
//   ro=0: row r, dir=fl      ro=2: row 3-r, dir=!fl
//   ro=1: col (fl?r:3-r) asc ro=3: col (fl?3-r:r) desc
// ---------------------------------------------------------------------------
__device__ __forceinline__ unsigned build_word(
    unsigned v, int r,
    const float* __restrict__ w0, const float* __restrict__ w1,
    const float* __restrict__ w2,
    const int* s_tbl, const int* sA, const int* sB, const int* sC)
{
    unsigned i = v;
    unsigned d = i % 17u; i /= 17u;
    unsigned c = i % 17u; i /= 17u;
    unsigned b = i % 17u;
    unsigned a = i / 17u;

    int key =  (int)(a <= b)
            | ((int)(a <= c) << 1)
            | ((int)(a <= d) << 2)
            | ((int)(b <= c) << 3)
            | ((int)(b <= d) << 4)
            | ((int)(c <= d) << 5);
    int packed = s_tbl[key];
    int ty = packed & 3;
    int ro = (packed >> 2) & 3;
    int fl = (packed >> 4) & 1;

    unsigned l0 = min(a, b), h0 = max(a, b);
    unsigned l1 = min(c, d), h1 = max(c, d);
    unsigned s0 = min(l0, l1), m0 = max(l0, l1);
    unsigned m1 = min(h0, h1), s3 = max(h0, h1);
    unsigned s1 = min(m0, m1), s2 = max(m0, m1);
    int widx = sA[s0] + sB[s1] + sC[s2] + (int)s3;

    int rr3  = 3 - r;
    bool odd = (ro & 1) != 0;

    int srow = (ro == 0) ? r : rr3;
    int dirR = fl ^ (ro >> 1);
    int baseR = srow * 4 + (dirR ? 3 : 0);
    int stepR = dirR ? -1 : 1;

    int scol = ((fl ^ (int)(ro == 3)) != 0) ? r : rr3;
    int dirC = (ro == 3);
    int baseC = (dirC ? 12 : 0) + scol;
    int stepC = dirC ? -4 : 4;

    int base = odd ? baseC : baseR;
    int step = odd ? stepC : stepR;

    const float* wp = (ty == 0) ? w0 : ((ty == 1) ? w1 : w2);
    const float* p  = wp + (unsigned)widx * 16u + base;

    float v0 = __ldg(p);
    float v1 = __ldg(p + step);
    float v2 = __ldg(p + 2 * step);
    float v3 = __ldg(p + 3 * step);

    int q0 = (int)fminf(fmaxf(rintf(v0), -128.0f), 127.0f);
    int q1 = (int)fminf(fmaxf(rintf(v1), -128.0f), 127.0f);
    int q2 = (int)fminf(fmaxf(rintf(v2), -128.0f), 127.0f);
    int q3 = (int)fminf(fmaxf(rintf(v3), -128.0f), 127.0f);

    return  ((unsigned)q0 & 0xffu)
         | (((unsigned)q1 & 0xffu) << 8)
         | (((unsigned)q2 & 0xffu) << 16)
         | (((unsigned)q3 & 0xffu) << 24);
}

// ---------------------------------------------------------------------------
// Kernel 1: materialize the int8 table. 2 values per thread (MLP=2 on the
// long-latency chain), 4 lanes per value.
// ---------------------------------------------------------------------------
#define BUILD_H 41761   // ceil(NVALS/2)

__global__ __launch_bounds__(256)
void build_table_kernel(const float* __restrict__ w0,
                        const float* __restrict__ w1,
                        const float* __restrict__ w2)
{
    __shared__ int s_tbl[64];
    __shared__ int sA[17], sB[17], sC[17];
    {
        int tid = threadIdx.x;
        if (tid < 64)                 s_tbl[tid]    = g_luts.tbl64[tid];
        if (tid >= 64  && tid < 81)   sA[tid - 64]  = g_luts.wA[tid - 64];
        if (tid >= 96  && tid < 113)  sB[tid - 96]  = g_luts.wB[tid - 96];
        if (tid >= 128 && tid < 145)  sC[tid - 128] = g_luts.wC[tid - 128];
    }
    __syncthreads();

    unsigned gid = blockIdx.x * blockDim.x + threadIdx.x;
    unsigned t = gid >> 2;            // base value slot
    int r = gid & 3;                  // row owned by this lane
    if (t >= BUILD_H) return;

    unsigned vA = t;
    unsigned vB = t + BUILD_H;

    unsigned wa = build_word(vA, r, w0, w1, w2, s_tbl, sA, sB, sC);
    g_tab8[vA * 4u + (unsigned)r] = wa;

    if (vB < NVALS) {
        unsigned wb = build_word(vB, r, w0, w1, w2, s_tbl, sA, sB, sC);
        g_tab8[vB * 4u + (unsigned)r] = wb;
    }
}

// ---------------------------------------------------------------------------
// Kernel 2: hot gather, UNROLL=8 indices per thread, 4 lanes per index.
// Group g handles indices g + k*S (S = concurrent groups) so every LDG/STG
// stays fully coalesced across the warp; 8 independent chains (MLP=8).
// TAIL=false variant is predicate-free (launched when n % UNROLL == 0 and
// the grid exactly covers n).
// ---------------------------------------------------------------------------
#define UNROLL 8

template <bool TAIL>
__global__ __launch_bounds__(256)
void gather_kernel(const int* __restrict__ index,
                   float4*    __restrict__ out,
                   int n, unsigned S)
{
    unsigned tid = blockIdx.x * blockDim.x + threadIdx.x;
    unsigned g = tid >> 2;              // group id
    int r = tid & 3;                    // row within tile

    unsigned v[UNROLL];
    unsigned w[UNROLL];

    #pragma unroll
    for (int k = 0; k < UNROLL; k++) {
        unsigned idx = g + (unsigned)k * S;
        bool ok = !TAIL || (idx < (unsigned)n);
        v[k] = ok ? (unsigned)__ldg(&index[idx]) : 0u;
    }
    #pragma unroll
    for (int k = 0; k < UNROLL; k++) {
        w[k] = __ldg(&g_tab8[v[k] * 4u + (unsigned)r]);
    }
    #pragma unroll
    for (int k = 0; k < UNROLL; k++) {
        unsigned idx = g + (unsigned)k * S;
        float o0 = (float)(int)((signed char)( w[k]        & 0xffu));
        float o1 = (float)(int)((signed char)((w[k] >> 8)  & 0xffu));
        float o2 = (float)(int)((signed char)((w[k] >> 16) & 0xffu));
        float o3 = (float)(int)((signed char)( w[k] >> 24));
        if (!TAIL || (idx < (unsigned)n)) {
            __stcs(&out[(size_t)idx * 4u + (unsigned)r],
                   make_float4(o0, o1, o2, o3));
        }
    }
}

// ---------------------------------------------------------------------------
// Harness entry
// ---------------------------------------------------------------------------
extern "C" void kernel_launch(void* const* d_in, const int* in_sizes, int n_in,
                              void* d_out, int out_size)
{
    const int*   index = (const int*)  d_in[0];
    const float* w0    = (const float*)d_in[1];
    const float* w1    = (const float*)d_in[2];
    const float* w2    = (const float*)d_in[3];
    float4*      out   = (float4*)     d_out;
    int n = in_sizes[0];

    // Pass 1: materialize all 17^4 tiles as int8 (1.3 MiB, L2-resident).
    {
        unsigned total = BUILD_H * 4u;
        unsigned block = 256;
        unsigned grid  = (total + block - 1) / block;
        build_table_kernel<<<grid, block>>>(w0, w1, w2);
    }
    // Pass 2: gather + s8->f32 expand, 8 indices per thread.
    {
        unsigned block  = 256;
        unsigned groups = ((unsigned)n + UNROLL - 1) / UNROLL;
        unsigned total  = groups * 4u;
        unsigned grid   = (total + block - 1) / block;
        // Predicate-free fast path when the launch exactly tiles n.
        if (((unsigned)n % UNROLL) == 0u && (total % block) == 0u) {
            gather_kernel<false><<<grid, block>>>(index, out, n, groups);
        } else {
            gather_kernel<true><<<grid, block>>>(index, out, n, groups);
        }
    }
}

// round 11
// speedup vs baseline: 1.0604x; 1.0604x over previous
#include <cuda_runtime.h>
#include <cstdint>

// ---------------------------------------------------------------------------
// Compile-time LUT construction (replicates the numpy table builders exactly)
// ---------------------------------------------------------------------------
struct LUTs {
    int tbl64[64];   // packed: ptype | rot<<2 | flip<<4, keyed by 6 pairwise <= bits
    int wA[17], wB[17], wC[17];  // lex-rank prefix tables for sorted tuples
};

static constexpr LUTs make_luts() {
    LUTs L = {};
    int tm[256] = {}, rm[256] = {}, fm[256] = {};
    for (int i = 0; i < 256; i++) { tm[i] = 10; rm[i] = 10; fm[i] = 10; }
    const int pats[3][4] = { {0,1,2,3}, {0,1,3,2}, {0,2,3,1} };
    for (int pt = 0; pt < 3; ++pt) {
        int p[4] = { pats[pt][0], pats[pt][1], pats[pt][2], pats[pt][3] };
        for (int fl = 0; fl < 2; ++fl) {
            for (int ro = 0; ro < 4; ++ro) {
                int q[4] = { p[0], p[1], p[2], p[3] };
                for (int k = 0; k < ro; k++) {           // np.rot90 once
                    int t0 = q[0], t1 = q[1], t2 = q[2], t3 = q[3];
                    q[0] = t1; q[1] = t3; q[2] = t0; q[3] = t2;
                }
                int id = ((q[0]*4 + q[1])*4 + q[2])*4 + q[3];
                tm[id] = pt; rm[id] = ro; fm[id] = fl;
            }
            int t0 = p[0], t1 = p[1], t2 = p[2], t3 = p[3]; // p = p[:, ::-1]
            p[0] = t1; p[1] = t0; p[2] = t3; p[3] = t2;
        }
    }
    for (int key = 0; key < 64; ++key) {
        int p01 =  key       & 1;
        int p02 = (key >> 1) & 1;
        int p03 = (key >> 2) & 1;
        int p12 = (key >> 3) & 1;
        int p13 = (key >> 4) & 1;
        int p23 = (key >> 5) & 1;
        int r0 = (1-p01) + (1-p02) + (1-p03);
        int r1 = p01 + (1-p12) + (1-p13);
        int r2 = p02 + p12 + (1-p23);
        int r3 = p03 + p13 + p23;
        int rr[4] = { r0, r1, r2, r3 };
        int seen[4] = {0,0,0,0};
        bool ok = true;
        for (int k = 0; k < 4; k++) {
            if (rr[k] < 0 || rr[k] > 3) { ok = false; break; }
            seen[rr[k]]++;
        }
        if (ok) for (int k = 0; k < 4; k++) if (seen[k] != 1) ok = false;
        int val = 0;
        if (ok) {
            int id = ((r0*4 + r1)*4 + r2)*4 + r3;
            int ty = tm[id], ro = rm[id], fl = fm[id];
            if (ty > 2) ty = 2;
            if (ro > 3) ro = 0;
            if (fl > 1) fl = 0;
            val = ty | (ro << 2) | (fl << 4);
        }
        L.tbl64[key] = val;
    }
    int S1 = 0, S2 = 0, S3 = 0;
    for (int x = 0; x < 17; ++x) {
        L.wA[x] = S3 - S2;
        L.wB[x] = S2 - S1;
        L.wC[x] = S1 - x;
        S1 += 17 - x;
        S2 += (18 - x) * (17 - x) / 2;
        S3 += (19 - x) * (18 - x) * (17 - x) / 6;
    }
    return L;
}

__constant__ LUTs g_luts = make_luts();

// Materialized output, quantized to int8 (values are exact integers in
// [-128,127] after round+clip). 17^4 tiles * 16 B = 1.3 MiB -> L2-resident.
// Layout: g_tab8[v*4 + r] packs row r of tile v as 4 s8 bytes (j=0 in LSB).
#define NVALS 83521
__device__ unsigned g_tab8[NVALS * 4];

// ---------------------------------------------------------------------------
// Kernel 1: materialize the int8 table. ONE THREAD PER VALUE:
//  - 4 independent LDG.128 load the whole 64B source tile (MLP=4)
//  - all 4 output rows computed in registers via row/col select + reversal
//    (same verified (ro,fl) mapping as rounds 5-10)
//  - one STG.128 writes the 16B table entry; consecutive v -> coalesced.
// ---------------------------------------------------------------------------
__global__ __launch_bounds__(256)
void build_table_kernel(const float* __restrict__ w0,
                        const float* __restrict__ w1,
                        const float* __restrict__ w2)
{
    __shared__ int s_tbl[64];
    __shared__ int sA[17], sB[17], sC[17];
    {
        int tid = threadIdx.x;
        if (tid < 64)                 s_tbl[tid]    = g_luts.tbl64[tid];
        if (tid >= 64  && tid < 81)   sA[tid - 64]  = g_luts.wA[tid - 64];
        if (tid >= 96  && tid < 113)  sB[tid - 96]  = g_luts.wB[tid - 96];
        if (tid >= 128 && tid < 145)  sC[tid - 128] = g_luts.wC[tid - 128];
    }
    __syncthreads();

    unsigned v = blockIdx.x * blockDim.x + threadIdx.x;
    if (v >= NVALS) return;

    // ---- decode base-17 digits ----
    unsigned i = v;
    unsigned d = i % 17u; i /= 17u;
    unsigned c = i % 17u; i /= 17u;
    unsigned b = i % 17u;
    unsigned a = i / 17u;

    // ---- symmetry class from pairwise comparison bits ----
    int key =  (int)(a <= b)
            | ((int)(a <= c) << 1)
            | ((int)(a <= d) << 2)
            | ((int)(b <= c) << 3)
            | ((int)(b <= d) << 4)
            | ((int)(c <= d) << 5);
    int packed = s_tbl[key];
    int ty = packed & 3;
    int ro = (packed >> 2) & 3;
    int fl = (packed >> 4) & 1;

    // ---- sort digits (network) -> lex rank -> widx ----
    unsigned l0 = min(a, b), h0 = max(a, b);
    unsigned l1 = min(c, d), h1 = max(c, d);
    unsigned s0 = min(l0, l1), m0 = max(l0, l1);
    unsigned m1 = min(h0, h1), s3 = max(h0, h1);
    unsigned s1 = min(m0, m1), s2 = max(m0, m1);
    int widx = sA[s0] + sB[s1] + sC[s2] + (int)s3;

    // ---- load full source tile: 4 independent LDG.128 ----
    const float* wp = (ty == 0) ? w0 : ((ty == 1) ? w1 : w2);
    const float4* tp = reinterpret_cast<const float4*>(wp + (unsigned)widx * 16u);
    float4 row0 = __ldg(tp + 0);
    float4 row1 = __ldg(tp + 1);
    float4 row2 = __ldg(tp + 2);
    float4 row3 = __ldg(tp + 3);

    // columns (free register picks): col[j] = (m[0][j], m[1][j], m[2][j], m[3][j])
    float4 col0 = make_float4(row0.x, row1.x, row2.x, row3.x);
    float4 col1 = make_float4(row0.y, row1.y, row2.y, row3.y);
    float4 col2 = make_float4(row0.z, row1.z, row2.z, row3.z);
    float4 col3 = make_float4(row0.w, row1.w, row2.w, row3.w);

    bool odd  = (ro & 1) != 0;
    int  dirR = fl ^ (ro >> 1);          // row reversal (ro even)
    bool revC = (ro == 3);               // col reversal (ro odd)
    bool rev  = odd ? revC : (dirR != 0);
    int  colSelFl = (fl ^ (int)(ro == 3));  // col index: colSelFl ? r : 3-r

    unsigned words[4];
    #pragma unroll
    for (int r = 0; r < 4; ++r) {
        int rr3 = 3 - r;
        int srow = (ro == 0) ? r : rr3;
        int scol = colSelFl ? r : rr3;
        int sidx = odd ? scol : srow;

        float4 e0 = odd ? col0 : row0;
        float4 e1 = odd ? col1 : row1;
        float4 e2 = odd ? col2 : row2;
        float4 e3 = odd ? col3 : row3;

        float4 src = (sidx == 0) ? e0 : (sidx == 1) ? e1 : (sidx == 2) ? e2 : e3;
        // Wait: when odd, we index COLUMNS by scol, i.e. pick col[scol].
        // e0..e3 above are col0..col3 in the odd case, row0..row3 otherwise,
        // so the single sidx select handles both cases.

        float f0 = rev ? src.w : src.x;
        float f1 = rev ? src.z : src.y;
        float f2 = rev ? src.y : src.z;
        float f3 = rev ? src.x : src.w;

        int q0 = (int)fminf(fmaxf(rintf(f0), -128.0f), 127.0f);
        int q1 = (int)fminf(fmaxf(rintf(f1), -128.0f), 127.0f);
        int q2 = (int)fminf(fmaxf(rintf(f2), -128.0f), 127.0f);
        int q3 = (int)fminf(fmaxf(rintf(f3), -128.0f), 127.0f);

        words[r] =  ((unsigned)q0 & 0xffu)
                 | (((unsigned)q1 & 0xffu) << 8)
                 | (((unsigned)q2 & 0xffu) << 16)
                 | (((unsigned)q3 & 0xffu) << 24);
    }

    // one 16B coalesced store per value
    *reinterpret_cast<uint4*>(&g_tab8[v * 4u]) =
        make_uint4(words[0], words[1], words[2], words[3]);
}

// ---------------------------------------------------------------------------
// Kernel 2: hot gather (unchanged from round 10 — at its structural floor).
// UNROLL=8 indices per thread, 4 lanes per index, S-strided for coalescing.
// ---------------------------------------------------------------------------
#define UNROLL 8

template <bool TAIL>
__global__ __launch_bounds__(256)
void gather_kernel(const int* __restrict__ index,
                   float4*    __restrict__ out,
                   int n, unsigned S)
{
    unsigned tid = blockIdx.x * blockDim.x + threadIdx.x;
    unsigned g = tid >> 2;              // group id
    int r = tid & 3;                    // row within tile

    unsigned v[UNROLL];
    unsigned w[UNROLL];

    #pragma unroll
    for (int k = 0; k < UNROLL; k++) {
        unsigned idx = g + (unsigned)k * S;
        bool ok = !TAIL || (idx < (unsigned)n);
        v[k] = ok ? (unsigned)__ldg(&index[idx]) : 0u;
    }
    #pragma unroll
    for (int k = 0; k < UNROLL; k++) {
        w[k] = __ldg(&g_tab8[v[k] * 4u + (unsigned)r]);
    }
    #pragma unroll
    for (int k = 0; k < UNROLL; k++) {
        unsigned idx = g + (unsigned)k * S;
        float o0 = (float)(int)((signed char)( w[k]        & 0xffu));
        float o1 = (float)(int)((signed char)((w[k] >> 8)  & 0xffu));
        float o2 = (float)(int)((signed char)((w[k] >> 16) & 0xffu));
        float o3 = (float)(int)((signed char)( w[k] >> 24));
        if (!TAIL || (idx < (unsigned)n)) {
            __stcs(&out[(size_t)idx * 4u + (unsigned)r],
                   make_float4(o0, o1, o2, o3));
        }
    }
}

// ---------------------------------------------------------------------------
// Harness entry
// ---------------------------------------------------------------------------
extern "C" void kernel_launch(void* const* d_in, const int* in_sizes, int n_in,
                              void* d_out, int out_size)
{
    const int*   index = (const int*)  d_in[0];
    const float* w0    = (const float*)d_in[1];
    const float* w1    = (const float*)d_in[2];
    const float* w2    = (const float*)d_in[3];
    float4*      out   = (float4*)     d_out;
    int n = in_sizes[0];

    // Pass 1: materialize all 17^4 tiles as int8 (1.3 MiB, L2-resident).
    {
        unsigned block = 256;
        unsigned grid  = (NVALS + block - 1) / block;
        build_table_kernel<<<grid, block>>>(w0, w1, w2);
    }
    // Pass 2: gather + s8->f32 expand, 8 indices per thread.
    {
        unsigned block  = 256;
        unsigned groups = ((unsigned)n + UNROLL - 1) / UNROLL;
        unsigned total  = groups * 4u;
        unsigned grid   = (total + block - 1) / block;
        if (((unsigned)n % UNROLL) == 0u && (total % block) == 0u) {
            gather_kernel<false><<<grid, block>>>(index, out, n, groups);
        } else {
            gather_kernel<true><<<grid, block>>>(index, out, n, groups);
        }
    }
}